// round 15
// baseline (speedup 1.0000x reference)
#include <cuda_runtime.h>

// BKT_RNN: B=8192, T=2048, H=4, X=1.
// R15: R12 (8 lanes/row, 2048 one-warp blocks, smem tau exchange, tau-form
// tanh sigmoids, closed-form latent, fused loss) WITHOUT the per-step
// __syncwarp. The inner loop is fully convergent (exchange ops are
// predicated, not branched); same-warp STS->LDS same-address is program-
// ordered in the LSU. Single-variable experiment vs R12 (207us): if the
// barrier was the stall source, expect ~140-165us.

#define TT 2048
#define BB 8192
#define NBLK (BB / 4)   // 2048 one-warp blocks, 4 rows per warp

__device__ float    g_part[NBLK];
__device__ unsigned g_done = 0;

__device__ __forceinline__ float lg2f(float v) {
    float r; asm("lg2.approx.f32 %0, %1;" : "=f"(r) : "f"(v)); return r;
}
__device__ __forceinline__ float tanhf_a(float v) {
    float r; asm("tanh.approx.f32 %0, %1;" : "=f"(r) : "f"(v)); return r;
}

__global__ void __launch_bounds__(32) k_bkt(
    const float* __restrict__ x,   const float* __restrict__ y,
    const float* __restrict__ Wxh, const float* __restrict__ Whh,
    const float* __restrict__ bh,  const float* __restrict__ Wy,
    const float* __restrict__ by,  const float* __restrict__ prior,
    float* __restrict__ corrects,  float* __restrict__ latents,
    float* __restrict__ loss)
{
    const unsigned FULL = 0xffffffffu;
    const int lane = threadIdx.x;
    const int i    = lane & 7;                  // role within 8-lane group
    const int j    = i & 3;                     // unit index
    const bool is_h = (i & 4) != 0;             // lanes 4-7: h units
    const int r    = lane >> 3;                 // row slot 0..3 in warp
    const int b    = blockIdx.x * 4 + r;

    // Double-buffered tau state per row: [parity][row][unit].
    __shared__ __align__(16) float tau_sm[2][4][4];

    // tau-form weights (sigmoid(z) = 0.5 + 0.5*tanh(z/2)):
    //   h-lane j: z/2 = 0.5*x*Wxh[j] + sum_m tau_m*(Whh[m][j]/4)
    //                   + (0.5*bh[j] + 0.25*sum_m Whh[m][j])
    //   p-lane j: z/2 = sum_m tau_m*(Wy[m][j]/4)
    //                   + (0.5*by[j] + 0.25*sum_m Wy[m][j])
    const float* Wsrc = is_h ? Whh : Wy;
    float Wc[4]; float sw = 0.f;
    #pragma unroll
    for (int m = 0; m < 4; m++) {
        const float w = __ldg(Wsrc + m * 4 + j);
        Wc[m] = 0.25f * w;
        sw   += w;
    }
    const float bias  = 0.5f * __ldg((is_h ? bh : by) + j) + 0.25f * sw;
    const float xcoef = is_h ? (0.5f * __ldg(Wxh + j)) : 0.f;

    // h = 0  ->  tau = -1. h-lanes initialize buffer 0.
    if (is_h) tau_sm[0][r][j] = -1.f;
    __syncwarp();    // one-time: ordering of the init only

    float lat  = __ldg(prior);     // tracked identically on lanes 0,1
    float lsum = 0.f;
    const bool odd     = (i & 1) != 0;
    const bool hi2     = (i & 2) != 0;
    const bool is_corr = ((i & 6) == 2);        // lanes 2,3: loss
    const bool is_out  = (i & 4) == 0;          // lanes 0-3 store

    const float4* xp = (const float4*)(x + (size_t)b * TT);
    const float4* yp = (const float4*)(y + (size_t)b * TT);
    // lanes 0/1 -> latents, lanes 2/3 -> corrects.
    float4* op = (float4*)(((i & 2) ? corrects : latents) + (size_t)b * TT);

    float4 xa = __ldcs(xp + 0), xb = __ldcs(xp + 1);
    float4 ya = __ldcs(yp + 0), yb = __ldcs(yp + 1);

    const int NCHUNK = TT / 8;
    for (int c = 0; c < NCHUNK; ++c) {
        float xv[8] = {xa.x, xa.y, xa.z, xa.w, xb.x, xb.y, xb.z, xb.w};
        float yv[8] = {ya.x, ya.y, ya.z, ya.w, yb.x, yb.y, yb.z, yb.w};

        if (c + 1 < NCHUNK) {   // prefetch next chunk under compute
            xa = __ldcs(xp + 2 * c + 2); xb = __ldcs(xp + 2 * c + 3);
            ya = __ldcs(yp + 2 * c + 2); yb = __ldcs(yp + 2 * c + 3);
        }

        float rb[8];
        float prod = 1.f;

        #pragma unroll
        for (int k = 0; k < 8; k++) {
            const int rd = k & 1;        // parity double-buffer; chunk size
            const int wr = 1 - rd;       //   even -> continuous across chunks

            // ---- all 4 taus of this row in ONE LDS.128 ----
            const float4 tv =
                *reinterpret_cast<const float4*>(&tau_sm[rd][r][0]);

            // ---- one dot + one tanh per lane (unified) ----
            const float zu = fmaf(tv.y, Wc[1],
                              fmaf(tv.x, Wc[0], fmaf(xv[k], xcoef, bias)));
            const float zv = fmaf(tv.w, Wc[3], tv.z * Wc[2]);
            const float tau = tanhf_a(zu + zv);

            // ---- h-lanes publish new tau (predicated STS, no branch) ----
            if (is_h) tau_sm[wr][r][j] = tau;

            // ---- latent / correct (p-lanes; tau-form) ----
            // lanes 0,1 (l,f): lat' = base + lat*coef  (local recurrence)
            // lanes 2,3 (g,s): correct = base + latc*coef (shfl-fed)
            const float taupo = __shfl_xor_sync(FULL, tau, 1);
            const float coef  = -0.5f * (tau + taupo);
            const float btau  = odd ? taupo : tau;
            const float base  = fmaf(0.5f, btau, 0.5f);
            const float latc  = __shfl_sync(FULL, lat, 0, 8);
            const float res_l = fmaf(lat,  coef, base);
            const float res_c = fmaf(latc, coef, base);
            lat = res_l;                 // meaningful on lanes 0,1
            const float res = hi2 ? res_c : res_l;
            rb[k] = res;

            // ---- loss (lanes 2,3; y in {0,1} -> one factor) ----
            const float cc = fminf(fmaxf(res, 1e-7f), 1.0f - 1e-7f);
            prod *= (yv[k] != 0.f) ? cc : (1.f - cc);
            if ((k & 3) == 3) {
                lsum += is_corr ? lg2f(prod) : 0.f;
                prod = 1.f;
            }
            // NO __syncwarp: convergent warp, program-ordered smem ops.
        }

        // lanes 0-3 store: even lane -> elems 0..3, odd -> 4..7.
        if (is_out) {
            const float4 v = odd ? make_float4(rb[4], rb[5], rb[6], rb[7])
                                 : make_float4(rb[0], rb[1], rb[2], rb[3]);
            __stcs(op + 2 * c + (odd ? 1 : 0), v);
        }
    }

    // Warp reduce (each row counted 2x: lanes 2,3) -> per-block slot.
    #pragma unroll
    for (int o = 16; o > 0; o >>= 1)
        lsum += __shfl_xor_sync(FULL, lsum, o);
    if (lane == 0)
        g_part[blockIdx.x] = lsum;
    __threadfence();

    // Last-block-done loss finalize.
    unsigned ticket = 0;
    if (lane == 0) ticket = atomicAdd(&g_done, 1u);
    ticket = __shfl_sync(FULL, ticket, 0);
    if (ticket == NBLK - 1) {
        double acc = 0.0;
        for (int t = lane; t < NBLK; t += 32)
            acc += (double)g_part[t];
        #pragma unroll
        for (int o = 16; o > 0; o >>= 1)
            acc += __shfl_xor_sync(FULL, acc, o);
        if (lane == 0) {
            loss[0] = (float)(-0.6931471805599453 * acc /
                              (2.0 * (double)BB * (double)TT));
            g_done = 0;   // re-arm for graph replay
        }
    }
}

extern "C" void kernel_launch(void* const* d_in, const int* in_sizes, int n_in,
                              void* d_out, int out_size) {
    const float* x     = (const float*)d_in[0];
    const float* y     = (const float*)d_in[1];
    const float* Wxh   = (const float*)d_in[2];
    const float* Whh   = (const float*)d_in[3];
    const float* bh    = (const float*)d_in[4];
    const float* Wy    = (const float*)d_in[5];
    const float* by    = (const float*)d_in[6];
    const float* prior = (const float*)d_in[7];

    float* corrects = (float*)d_out;
    float* latents  = (float*)d_out + (size_t)BB * TT;
    float* loss     = (float*)d_out + 2 * (size_t)BB * TT;

    k_bkt<<<NBLK, 32>>>(x, y, Wxh, Whh, bh, Wy, by, prior,
                        corrects, latents, loss);
}

// round 16
// speedup vs baseline: 1.0353x; 1.0353x over previous
#include <cuda_runtime.h>

// BKT_RNN: B=8192, T=2048, H=4, X=1.
// R16: R11 shape (4 lanes/row, 8 rows/warp, 1024 one-warp blocks, tau-form
// tanh sigmoids, closed-form latent, fused loss) with the 4x-redundant tau
// computation replaced by a shared-memory exchange: lane j computes ONE tau
// tanh (own unit) + ONE p tanh  ->  MUFU warp-ops/step drop 5.25 -> 2.25.
// MUFU (not shown in ncu's pipe summary) is the hypothesized binder.
// Exchange: parity double-buffered tau_sm[2][8][4]; STS 4B per lane, one
// LDS.128 per lane next step; no per-step syncwarp (validated in R15).

#define TT 2048
#define BB 8192
#define NBLK (BB / 8)   // 1024 one-warp blocks

__device__ float    g_part[NBLK];
__device__ unsigned g_done = 0;

__device__ __forceinline__ float lg2f(float v) {
    float r; asm("lg2.approx.f32 %0, %1;" : "=f"(r) : "f"(v)); return r;
}
__device__ __forceinline__ float tanhf_a(float v) {
    float r; asm("tanh.approx.f32 %0, %1;" : "=f"(r) : "f"(v)); return r;
}

__global__ void __launch_bounds__(32) k_bkt(
    const float* __restrict__ x,   const float* __restrict__ y,
    const float* __restrict__ Wxh, const float* __restrict__ Whh,
    const float* __restrict__ bh,  const float* __restrict__ Wy,
    const float* __restrict__ by,  const float* __restrict__ prior,
    float* __restrict__ corrects,  float* __restrict__ latents,
    float* __restrict__ loss)
{
    const unsigned FULL = 0xffffffffu;
    const int lane = threadIdx.x;
    const int j = lane & 3;                    // unit owned by this lane
    const int g = lane >> 2;                   // row group 0..7
    const int b = blockIdx.x * 8 + g;

    // Parity double-buffered tau state: [parity][group][unit], 16B rows.
    __shared__ __align__(16) float tau_sm[2][8][4];

    // tau-form weights (sigmoid(z) = 0.5 + 0.5*tanh(z/2)):
    //   h unit j: z/2 = 0.5*x*Wxh[j] + sum_m tau_m*(Whh[m][j]/4)
    //                   + (0.5*bh[j] + 0.25*sum_m Whh[m][j])
    //   p unit j: z/2 = sum_m tau_m*(Wy[m][j]/4)
    //                   + (0.5*by[j] + 0.25*sum_m Wy[m][j])
    float Wc[4], Pc[4];
    float sWh = 0.f, sWy = 0.f;
    #pragma unroll
    for (int m = 0; m < 4; m++) {
        const float wh = __ldg(Whh + m * 4 + j);
        const float wy = __ldg(Wy  + m * 4 + j);
        Wc[m] = 0.25f * wh;  sWh += wh;
        Pc[m] = 0.25f * wy;  sWy += wy;
    }
    const float bias_h = 0.5f * __ldg(bh + j) + 0.25f * sWh;
    const float bias_p = 0.5f * __ldg(by + j) + 0.25f * sWy;
    const float xcoef  = 0.5f * __ldg(Wxh + j);

    // h = 0 -> tau = -1. Every lane inits its own slot in buffer 0.
    tau_sm[0][g][j] = -1.f;
    __syncwarp();   // one-time ordering of the init

    float lat  = __ldg(prior);     // local recurrence (valid on lanes 0,1)
    float lsum = 0.f;
    const bool odd = (lane & 1) != 0;
    const bool hi2 = (lane & 2) != 0;          // lanes 2,3 -> correct series

    const float4* xp = (const float4*)(x + (size_t)b * TT);
    const float4* yp = (const float4*)(y + (size_t)b * TT);
    // Lanes 0/1 write latents, lanes 2/3 write corrects.
    float4* op = (float4*)((hi2 ? corrects : latents) + (size_t)b * TT);

    float4 xa = __ldcs(xp + 0), xb = __ldcs(xp + 1);
    float4 ya = __ldcs(yp + 0), yb = __ldcs(yp + 1);

    const int NCHUNK = TT / 8;
    for (int c = 0; c < NCHUNK; ++c) {
        float xv[8] = {xa.x, xa.y, xa.z, xa.w, xb.x, xb.y, xb.z, xb.w};
        float yv[8] = {ya.x, ya.y, ya.z, ya.w, yb.x, yb.y, yb.z, yb.w};

        if (c + 1 < NCHUNK) {   // prefetch next chunk under compute
            xa = __ldcs(xp + 2 * c + 2); xb = __ldcs(xp + 2 * c + 3);
            ya = __ldcs(yp + 2 * c + 2); yb = __ldcs(yp + 2 * c + 3);
        }

        float rb[8];
        float prod = 1.f;

        #pragma unroll
        for (int k = 0; k < 8; k++) {
            const int rd = k & 1;       // global step parity (8c even)
            const int wr = 1 - rd;

            // ---- all 4 taus of this row in ONE LDS.128 ----
            const float4 tv =
                *reinterpret_cast<const float4*>(&tau_sm[rd][g][0]);

            // ---- own h unit: dot + tanh; publish ----
            const float zhu = fmaf(tv.y, Wc[1],
                               fmaf(tv.x, Wc[0], fmaf(xv[k], xcoef, bias_h)));
            const float zhv = fmaf(tv.w, Wc[3], tv.z * Wc[2]);
            const float tau = tanhf_a(zhu + zhv);
            tau_sm[wr][g][j] = tau;      // STS 4B, conflict-free

            // ---- own p unit: dot + tanh (OLD taus) ----
            const float zpu = fmaf(tv.y, Pc[1], fmaf(tv.x, Pc[0], bias_p));
            const float zpv = fmaf(tv.w, Pc[3], tv.z * Pc[2]);
            const float taup = tanhf_a(zpu + zpv);  // p_j = 0.5+0.5*taup

            // ---- latent / correct (tau-form, unified; R11 form) ----
            // lanes 0,1 (l,f): lat' = base + lat*coef
            // lanes 2,3 (g,s): correct = base + latc*coef
            const float taupo = __shfl_xor_sync(FULL, taup, 1);
            const float coef  = -0.5f * (taup + taupo);
            const float btau  = odd ? taupo : taup;
            const float base  = fmaf(0.5f, btau, 0.5f);
            const float latc  = __shfl_sync(FULL, lat, 0, 4);  // old lat
            const float res   = fmaf(hi2 ? latc : lat, coef, base);
            lat = res;                 // meaningful on lanes 0,1
            rb[k] = res;

            // ---- loss (lanes 2,3; y in {0,1} -> one factor) ----
            const float cc = fminf(fmaxf(res, 1e-7f), 1.0f - 1e-7f);
            prod *= (yv[k] != 0.f) ? cc : (1.f - cc);
            if ((k & 3) == 3) {
                lsum += hi2 ? lg2f(prod) : 0.f;
                prod = 1.f;
            }
            // no per-step __syncwarp: convergent warp, same-warp smem
            // program order (validated R15: rel_err unchanged).
        }

        const float4 v = odd ? make_float4(rb[4], rb[5], rb[6], rb[7])
                             : make_float4(rb[0], rb[1], rb[2], rb[3]);
        __stcs(op + 2 * c + (odd ? 1 : 0), v);
    }

    // Warp reduce (each row counted 2x: lanes 2,3) -> per-block slot.
    #pragma unroll
    for (int o = 16; o > 0; o >>= 1)
        lsum += __shfl_xor_sync(FULL, lsum, o);
    if (lane == 0)
        g_part[blockIdx.x] = lsum;
    __threadfence();

    // Last-block-done loss finalize.
    unsigned ticket = 0;
    if (lane == 0) ticket = atomicAdd(&g_done, 1u);
    ticket = __shfl_sync(FULL, ticket, 0);
    if (ticket == NBLK - 1) {
        double acc = 0.0;
        for (int i = lane; i < NBLK; i += 32)
            acc += (double)g_part[i];
        #pragma unroll
        for (int o = 16; o > 0; o >>= 1)
            acc += __shfl_xor_sync(FULL, acc, o);
        if (lane == 0) {
            loss[0] = (float)(-0.6931471805599453 * acc /
                              (2.0 * (double)BB * (double)TT));
            g_done = 0;   // re-arm for graph replay
        }
    }
}

extern "C" void kernel_launch(void* const* d_in, const int* in_sizes, int n_in,
                              void* d_out, int out_size) {
    const float* x     = (const float*)d_in[0];
    const float* y     = (const float*)d_in[1];
    const float* Wxh   = (const float*)d_in[2];
    const float* Whh   = (const float*)d_in[3];
    const float* bh    = (const float*)d_in[4];
    const float* Wy    = (const float*)d_in[5];
    const float* by    = (const float*)d_in[6];
    const float* prior = (const float*)d_in[7];

    float* corrects = (float*)d_out;
    float* latents  = (float*)d_out + (size_t)BB * TT;
    float* loss     = (float*)d_out + 2 * (size_t)BB * TT;

    k_bkt<<<NBLK, 32>>>(x, y, Wxh, Whh, bh, Wy, by, prior,
                        corrects, latents, loss);
}

// round 17
// speedup vs baseline: 1.1268x; 1.0884x over previous
#include <cuda_runtime.h>

// BKT_RNN: B=8192, T=2048, H=4, X=1.
// R17: time-tiled two-phase execution. Per 32-step tile:
//  Phase A (serial, minimal): R16's smem tau exchange recurrence, body =
//    LDS.128 + 3-FMA tree + tanh + STS (~8 instr/step), writing the full
//    tau history tau_hist[row][slot][unit] (slot k = tau ENTERING step k).
//  Phase B (parallel over time): lane k owns timestep k; per row: LDS.128
//    tau vector, 4 p-tanh (throughput work), affine Hillis-Steele latent
//    scan (validated R9), correct, coalesced STG.32 outputs, loss.
// 4 lanes/row in phase A, 8 rows/warp, 1024 one-warp blocks. tau-form
// sigmoids (R10), fused last-block loss. No per-step syncwarp (R15/R16).

#define TT 2048
#define BB 8192
#define NBLK (BB / 8)    // 1024 one-warp blocks
#define S  32            // tile size (timesteps)
#define NT (TT / S)      // 64 tiles

__device__ float    g_part[NBLK];
__device__ unsigned g_done = 0;

__device__ __forceinline__ float lg2f(float v) {
    float r; asm("lg2.approx.f32 %0, %1;" : "=f"(r) : "f"(v)); return r;
}
__device__ __forceinline__ float tanhf_a(float v) {
    float r; asm("tanh.approx.f32 %0, %1;" : "=f"(r) : "f"(v)); return r;
}

__global__ void __launch_bounds__(32) k_bkt(
    const float* __restrict__ x,   const float* __restrict__ y,
    const float* __restrict__ Wxh, const float* __restrict__ Whh,
    const float* __restrict__ bh,  const float* __restrict__ Wy,
    const float* __restrict__ by,  const float* __restrict__ prior,
    float* __restrict__ corrects,  float* __restrict__ latents,
    float* __restrict__ loss)
{
    const unsigned FULL = 0xffffffffu;
    const int lane = threadIdx.x;
    const int j = lane & 3;                    // unit (phase A)
    const int g = lane >> 2;                   // row group (phase A)
    const int rowbase = blockIdx.x * 8;

    // tau history: [row][slot 0..32][unit]; slot k = tau entering step k.
    // Row stride 33*4 floats = 528B (16B-aligned); slot stride 16B.
    __shared__ __align__(16) float tau_hist[8][33][4];
    // Staged inputs, padded to 36 floats (144B, 16B-aligned rows;
    // broadcast reads conflict-free: bank (4g+k)%32 over g).
    __shared__ __align__(16) float x_sm[8][36];
    __shared__ __align__(16) float y_sm[8][36];

    // tau-form weights (sigmoid(z) = 0.5 + 0.5*tanh(z/2)):
    //   h unit j (phase A, own column only):
    //     z/2 = 0.5 x Wxh[j] + sum_m tau_m (Whh[m][j]/4)
    //           + (0.5 bh[j] + 0.25 sum_m Whh[m][j])
    //   p units (phase B, FULL Wy on every lane):
    //     zp_jj/2 = sum_m tau_m (Wy[m][jj]/4) + (0.5 by[jj] + 0.25 sum_m Wy[m][jj])
    float Wc[4]; float sWh = 0.f;
    #pragma unroll
    for (int m = 0; m < 4; m++) {
        const float w = __ldg(Whh + m * 4 + j);
        Wc[m] = 0.25f * w;  sWh += w;
    }
    const float bias_h = 0.5f * __ldg(bh + j) + 0.25f * sWh;
    const float xcoef  = 0.5f * __ldg(Wxh + j);

    float P[4][4], pb[4];
    #pragma unroll
    for (int jj = 0; jj < 4; jj++) {
        float sWy = 0.f;
        #pragma unroll
        for (int m = 0; m < 4; m++) {
            const float w = __ldg(Wy + m * 4 + jj);
            P[m][jj] = 0.25f * w;  sWy += w;
        }
        pb[jj] = 0.5f * __ldg(by + jj) + 0.25f * sWy;
    }

    float tau = -1.f;                  // h = 0 -> tau = -1
    float lat[8];
    const float pr = __ldg(prior);
    #pragma unroll
    for (int r = 0; r < 8; r++) lat[r] = pr;
    float lsum = 0.f, prod = 1.f;

    // Staging map: idx = row*8 + seg (8 float4 segs per row-tile).
    // Lane L handles idx L (row L>>3, seg L&7) and idx L+32 (row 4+(L>>3)).
    const int r0 = lane >> 3, sg = lane & 7;
    const float4* xpA = (const float4*)(x + (size_t)(rowbase + r0    ) * TT);
    const float4* xpB = (const float4*)(x + (size_t)(rowbase + r0 + 4) * TT);
    const float4* ypA = (const float4*)(y + (size_t)(rowbase + r0    ) * TT);
    const float4* ypB = (const float4*)(y + (size_t)(rowbase + r0 + 4) * TT);

    // Prefetch tile 0.
    float4 px0 = __ldcs(xpA + sg), px1 = __ldcs(xpB + sg);
    float4 py0 = __ldcs(ypA + sg), py1 = __ldcs(ypB + sg);

    for (int tile = 0; tile < NT; ++tile) {
        // ---- stage current tile's x/y; publish entering tau ----
        *(float4*)&x_sm[r0    ][sg * 4] = px0;
        *(float4*)&x_sm[r0 + 4][sg * 4] = px1;
        *(float4*)&y_sm[r0    ][sg * 4] = py0;
        *(float4*)&y_sm[r0 + 4][sg * 4] = py1;
        tau_hist[g][0][j] = tau;

        // ---- prefetch next tile under this tile's compute ----
        if (tile + 1 < NT) {
            const int o = (tile + 1) * 8 + sg;
            px0 = __ldcs(xpA + o); px1 = __ldcs(xpB + o);
            py0 = __ldcs(ypA + o); py1 = __ldcs(ypB + o);
        }

        // ---- Phase A: serial tau recurrence (minimal body) ----
        #pragma unroll
        for (int k = 0; k < S; k++) {
            const float4 tv = *(const float4*)&tau_hist[g][k][0];
            const float xt  = x_sm[g][k];
            const float zu  = fmaf(tv.y, Wc[1],
                               fmaf(tv.x, Wc[0], fmaf(xt, xcoef, bias_h)));
            const float zv  = fmaf(tv.w, Wc[3], tv.z * Wc[2]);
            tau = tanhf_a(zu + zv);
            tau_hist[g][k + 1][j] = tau;
        }

        // ---- Phase B: parallel over time (lane k = timestep k) ----
        const int tb = tile * S;
        #pragma unroll
        for (int r = 0; r < 8; r++) {
            const float4 pv = *(const float4*)&tau_hist[r][lane][0];

            // 4 p-taus for (row r, step lane)
            const float z0 = fmaf(pv.y, P[1][0], fmaf(pv.x, P[0][0], pb[0])) +
                             fmaf(pv.w, P[3][0], pv.z * P[2][0]);
            const float z1 = fmaf(pv.y, P[1][1], fmaf(pv.x, P[0][1], pb[1])) +
                             fmaf(pv.w, P[3][1], pv.z * P[2][1]);
            const float z2 = fmaf(pv.y, P[1][2], fmaf(pv.x, P[0][2], pb[2])) +
                             fmaf(pv.w, P[3][2], pv.z * P[2][2]);
            const float z3 = fmaf(pv.y, P[1][3], fmaf(pv.x, P[0][3], pb[3])) +
                             fmaf(pv.w, P[3][3], pv.z * P[2][3]);
            const float tl = tanhf_a(z0);
            const float tf = tanhf_a(z1);
            const float tg = tanhf_a(z2);
            const float ts = tanhf_a(z3);

            // affine latent step: lat' = C*lat + Bv ; correct = cg*lat_in + bg
            float C  = -0.5f * (tl + tf);
            float Bv = fmaf(0.5f, tl, 0.5f);
            const float cg = -0.5f * (tg + ts);
            const float bg = fmaf(0.5f, tg, 0.5f);

            // Hillis-Steele inclusive scan over 32 steps (validated R9).
            #pragma unroll
            for (int off = 1; off < 32; off <<= 1) {
                const float c2 = __shfl_up_sync(FULL, C,  off);
                const float b2 = __shfl_up_sync(FULL, Bv, off);
                if (lane >= off) { Bv = fmaf(b2, C, Bv); C *= c2; }
            }
            float Cex = __shfl_up_sync(FULL, C,  1);
            float Bex = __shfl_up_sync(FULL, Bv, 1);
            if (lane == 0) { Cex = 1.f; Bex = 0.f; }

            const float Lent = fmaf(lat[r], Cex, Bex);  // latent entering
            const float Laft = fmaf(lat[r], C,   Bv);   // latent after
            const float corr = fmaf(Lent, cg, bg);

            __stcs(corrects + (size_t)(rowbase + r) * TT + tb + lane, corr);
            __stcs(latents  + (size_t)(rowbase + r) * TT + tb + lane, Laft);

            // loss (every (row,step) exactly once, this lane)
            const float cc = fminf(fmaxf(corr, 1e-7f), 1.0f - 1e-7f);
            const float yv = y_sm[r][lane];
            prod *= (yv != 0.f) ? cc : (1.f - cc);
            if ((r & 3) == 3) { lsum += lg2f(prod); prod = 1.f; }

            lat[r] = __shfl_sync(FULL, Laft, 31);       // tile carry
        }
    }

    // ---- loss: warp reduce -> per-block slot -> last-block finalize ----
    #pragma unroll
    for (int o = 16; o > 0; o >>= 1)
        lsum += __shfl_xor_sync(FULL, lsum, o);
    if (lane == 0)
        g_part[blockIdx.x] = lsum;
    __threadfence();

    unsigned ticket = 0;
    if (lane == 0) ticket = atomicAdd(&g_done, 1u);
    ticket = __shfl_sync(FULL, ticket, 0);
    if (ticket == NBLK - 1) {
        double acc = 0.0;
        for (int i = lane; i < NBLK; i += 32)
            acc += (double)g_part[i];
        #pragma unroll
        for (int o = 16; o > 0; o >>= 1)
            acc += __shfl_xor_sync(FULL, acc, o);
        if (lane == 0) {
            loss[0] = (float)(-0.6931471805599453 * acc /
                              ((double)BB * (double)TT));
            g_done = 0;   // re-arm for graph replay
        }
    }
}

extern "C" void kernel_launch(void* const* d_in, const int* in_sizes, int n_in,
                              void* d_out, int out_size) {
    const float* x     = (const float*)d_in[0];
    const float* y     = (const float*)d_in[1];
    const float* Wxh   = (const float*)d_in[2];
    const float* Whh   = (const float*)d_in[3];
    const float* bh    = (const float*)d_in[4];
    const float* Wy    = (const float*)d_in[5];
    const float* by    = (const float*)d_in[6];
    const float* prior = (const float*)d_in[7];

    float* corrects = (float*)d_out;
    float* latents  = (float*)d_out + (size_t)BB * TT;
    float* loss     = (float*)d_out + 2 * (size_t)BB * TT;

    k_bkt<<<NBLK, 32>>>(x, y, Wxh, Whh, bh, Wy, by, prior,
                        corrects, latents, loss);
}